// round 9
// baseline (speedup 1.0000x reference)
#include <cuda_runtime.h>
#include <cstdint>
#include <cstddef>

#define BATCH 32
#define SEQT  2048
#define INSZ  512
#define HID   512
#define G3    1536
#define NT    256
#define CLC   16
#define NCLU  8
typedef unsigned long long ull;

__device__ float g_xg[(size_t)SEQT * BATCH * G3];   // [t][b][3H]
__device__ float g_h[2][BATCH * HID];

// ---- packed f32x2 helpers ----
__device__ __forceinline__ ull pk2(float x, float y) {
  ull r; asm("mov.b64 %0, {%1,%2};" : "=l"(r) : "f"(x), "f"(y)); return r;
}
__device__ __forceinline__ ull ffma2(ull a, ull b, ull c) {
  ull d; asm("fma.rn.f32x2 %0, %1, %2, %3;" : "=l"(d) : "l"(a), "l"(b), "l"(c)); return d;
}
__device__ __forceinline__ float2 upk2(ull v) {
  float x, y; asm("mov.b64 {%0,%1}, %2;" : "=f"(x), "=f"(y) : "l"(v));
  return make_float2(x, y);
}
__device__ __forceinline__ float sigmoid_f(float x) { return 1.f / (1.f + __expf(-x)); }
__device__ __forceinline__ float tanh_f(float x) {
  float e = __expf(-2.f * x); return (1.f - e) / (1.f + e);
}

// =============================================================
// Kernel A: x_gates = input @ W_ih^T + b_ih  (R8 design, unchanged)
// =============================================================
__global__ __launch_bounds__(256, 1) void gemm_xgates(
    const float* __restrict__ A, const float* __restrict__ Wih,
    const float* __restrict__ bih) {
  __shared__ ull As2[2][8][128];
  __shared__ ull Bs2[2][8][128];

  const int tid = threadIdx.x;
  const int m0 = blockIdx.y << 7, n0 = blockIdx.x << 7;
  const int tx = tid & 15, ty = tid >> 4;
  const int lrow = tid & 127, lk4 = (tid >> 7) << 3;
  const int ty4 = ty * 4;

  const float* Ap = A + (size_t)(m0 + lrow) * INSZ + lk4;
  const float* Bp = Wih + (size_t)(n0 + lrow) * INSZ + lk4;

  ull acc[64];
#pragma unroll
  for (int i = 0; i < 64; i++) acc[i] = 0ull;

  float4 la0 = *(const float4*)(Ap), la1 = *(const float4*)(Ap + 4);
  float4 lb0 = *(const float4*)(Bp), lb1 = *(const float4*)(Bp + 4);
  {
    int kk = lk4 >> 1;
    As2[0][kk + 0][lrow] = pk2(la0.x, la0.y);
    As2[0][kk + 1][lrow] = pk2(la0.z, la0.w);
    As2[0][kk + 2][lrow] = pk2(la1.x, la1.y);
    As2[0][kk + 3][lrow] = pk2(la1.z, la1.w);
    Bs2[0][kk + 0][lrow] = pk2(lb0.x, lb0.y);
    Bs2[0][kk + 1][lrow] = pk2(lb0.z, lb0.w);
    Bs2[0][kk + 2][lrow] = pk2(lb1.x, lb1.y);
    Bs2[0][kk + 3][lrow] = pk2(lb1.z, lb1.w);
  }
  __syncthreads();

  for (int kt = 0; kt < 32; kt++) {
    const int cur = kt & 1, nxt = cur ^ 1;
    if (kt < 31) {
      Ap += 16; Bp += 16;
      la0 = *(const float4*)(Ap); la1 = *(const float4*)(Ap + 4);
      lb0 = *(const float4*)(Bp); lb1 = *(const float4*)(Bp + 4);
    }
#pragma unroll
    for (int kk = 0; kk < 8; kk++) {
      ulonglong2 aa0 = *(const ulonglong2*)&As2[cur][kk][ty4];
      ulonglong2 aa1 = *(const ulonglong2*)&As2[cur][kk][ty4 + 2];
      ulonglong2 aa2 = *(const ulonglong2*)&As2[cur][kk][64 + ty4];
      ulonglong2 aa3 = *(const ulonglong2*)&As2[cur][kk][64 + ty4 + 2];
      ulonglong2 bb0 = *(const ulonglong2*)&Bs2[cur][kk][tx * 4];
      ulonglong2 bb1 = *(const ulonglong2*)&Bs2[cur][kk][tx * 4 + 2];
      ulonglong2 bb2 = *(const ulonglong2*)&Bs2[cur][kk][64 + tx * 4];
      ulonglong2 bb3 = *(const ulonglong2*)&Bs2[cur][kk][64 + tx * 4 + 2];
      ull a2[8] = {aa0.x, aa0.y, aa1.x, aa1.y, aa2.x, aa2.y, aa3.x, aa3.y};
      ull b2[8] = {bb0.x, bb0.y, bb1.x, bb1.y, bb2.x, bb2.y, bb3.x, bb3.y};
#pragma unroll
      for (int i = 0; i < 8; i++)
#pragma unroll
        for (int j = 0; j < 8; j++)
          acc[i * 8 + j] = ffma2(a2[i], b2[j], acc[i * 8 + j]);
    }
    if (kt < 31) {
      int kk = lk4 >> 1;
      As2[nxt][kk + 0][lrow] = pk2(la0.x, la0.y);
      As2[nxt][kk + 1][lrow] = pk2(la0.z, la0.w);
      As2[nxt][kk + 2][lrow] = pk2(la1.x, la1.y);
      As2[nxt][kk + 3][lrow] = pk2(la1.z, la1.w);
      Bs2[nxt][kk + 0][lrow] = pk2(lb0.x, lb0.y);
      Bs2[nxt][kk + 1][lrow] = pk2(lb0.z, lb0.w);
      Bs2[nxt][kk + 2][lrow] = pk2(lb1.x, lb1.y);
      Bs2[nxt][kk + 3][lrow] = pk2(lb1.z, lb1.w);
    }
    __syncthreads();
  }

  float4 bia0 = *(const float4*)(bih + n0 + tx * 4);
  float4 bia1 = *(const float4*)(bih + n0 + 64 + tx * 4);
#pragma unroll
  for (int i = 0; i < 8; i++) {
    int m = m0 + ((i < 4) ? (ty4 + i) : (64 + ty4 + i - 4));
    int b = m >> 11, t = m & 2047;
    float* orow = g_xg + ((size_t)t * BATCH + b) * G3 + n0;
    float2 p; float4 o0, o1;
    p = upk2(acc[i * 8 + 0]); o0.x = p.x + p.y + bia0.x;
    p = upk2(acc[i * 8 + 1]); o0.y = p.x + p.y + bia0.y;
    p = upk2(acc[i * 8 + 2]); o0.z = p.x + p.y + bia0.z;
    p = upk2(acc[i * 8 + 3]); o0.w = p.x + p.y + bia0.w;
    p = upk2(acc[i * 8 + 4]); o1.x = p.x + p.y + bia1.x;
    p = upk2(acc[i * 8 + 5]); o1.y = p.x + p.y + bia1.y;
    p = upk2(acc[i * 8 + 6]); o1.z = p.x + p.y + bia1.z;
    p = upk2(acc[i * 8 + 7]); o1.w = p.x + p.y + bia1.w;
    *(float4*)(orow + tx * 4) = o0;
    *(float4*)(orow + 64 + tx * 4) = o1;
  }
}

// =============================================================
// Kernel B: cluster-synchronized persistent GRU scan (R6/R8, unchanged)
// =============================================================
#define SCAN_SMEM 208256

__global__ __launch_bounds__(NT, 1) __cluster_dims__(CLC, 1, 1)
void gru_scan(const float* __restrict__ Whh, const float* __restrict__ bhh,
              const float* __restrict__ h0, float* __restrict__ out) {
  extern __shared__ char smem[];
  char* WS = smem;
  char* HS = smem + 196608;
  float* red = (float*)(smem + 204800);
  float* bh  = (float*)(smem + 207872);

  const int tid = threadIdx.x;
  const int grp = blockIdx.x >> 4;
  const int cid = blockIdx.x & 15;
  const int j0  = cid << 5;
  const int b0g = grp << 2;

  const int w = tid >> 5, lane = tid & 31;
  const int kh = w & 1;
  const int bb = lane >> 3, ko = lane & 7;

  for (int idx = tid; idx < 96 * 128; idx += NT) {
    int r = idx >> 7, c4 = idx & 127;
    int jj = r / 3, g = r - jj * 3;
    float4 v = *(const float4*)(Whh + (size_t)(g * HID + j0 + jj) * HID + (c4 << 2));
    int kh2 = c4 >> 6, rem = c4 & 63, ko2 = rem >> 3, s = rem & 7;
    int jp2 = jj >> 3, jl = jj & 7, rr = jl * 3 + g;
    *(float4*)(WS + ((jp2 * 2 + kh2) * 24 + rr) * 1024 + s * 128 + ko2 * 16) = v;
  }
  if (tid < 96) {
    int jj = tid / 3, g = tid - jj * 3;
    bh[tid] = bhh[g * HID + j0 + jj];
  }
  if (tid < 128) {
    int b_o = tid >> 5, jj_o = tid & 31;
    g_h[0][(b0g + b_o) * HID + j0 + jj_o] = h0[(b0g + b_o) * HID + j0 + jj_o];
  }
  asm volatile("barrier.cluster.arrive.aligned;" ::: "memory");
  asm volatile("barrier.cluster.wait.aligned;" ::: "memory");

  for (int t = 0; t < SEQT; t++) {
    const float* hp = g_h[t & 1];
    float* hn = g_h[(t + 1) & 1];

    const int b_o = tid >> 5, jj_o = tid & 31;
    float xr = 0.f, xz = 0.f, xn = 0.f, hprev = 0.f;
    if (tid < 128) {
      const float* xgp = g_xg + ((size_t)t * BATCH + (b0g + b_o)) * G3 + j0 + jj_o;
      xr = __ldcg(xgp); xz = __ldcg(xgp + HID); xn = __ldcg(xgp + 2 * HID);
      hprev = __ldcg(hp + (b0g + b_o) * HID + j0 + jj_o);
    }

#pragma unroll
    for (int i = 0; i < 2; i++) {
      int idx = i * NT + tid;
      int b_r = idx >> 7, c4 = idx & 127;
      int kh2 = c4 >> 6, rem = c4 & 63, ko2 = rem >> 3, s = rem & 7;
      const float* src = hp + (b0g + b_r) * HID + (c4 << 2);
      float4 v;
      asm volatile("ld.global.cg.v4.f32 {%0,%1,%2,%3},[%4];"
                   : "=f"(v.x), "=f"(v.y), "=f"(v.z), "=f"(v.w) : "l"(src));
      *(float4*)(HS + kh2 * 4096 + s * 512 + b_r * 128 + ko2 * 16) = v;
    }
    __syncthreads();

    ull hx[8], hy[8];
    const char* hb = HS + kh * 4096 + bb * 128 + ko * 16;
#pragma unroll
    for (int s = 0; s < 8; s++) {
      ulonglong2 u = *(const ulonglong2*)(hb + s * 512);
      hx[s] = u.x; hy[s] = u.y;
    }

    ull acc[24];
#pragma unroll
    for (int r = 0; r < 24; r++) acc[r] = 0ull;
    const char* wb = WS + (w * 24) * 1024 + ko * 16;
#pragma unroll
    for (int s = 0; s < 8; s++) {
      const char* wbs = wb + s * 128;
#pragma unroll
      for (int r = 0; r < 24; r++) {
        ulonglong2 u = *(const ulonglong2*)(wbs + r * 1024);
        acc[r] = ffma2(u.x, hx[s], acc[r]);
        acc[r] = ffma2(u.y, hy[s], acc[r]);
      }
    }

#pragma unroll
    for (int r = 0; r < 24; r++) {
      float2 p = upk2(acc[r]);
      float v = p.x + p.y;
      v += __shfl_xor_sync(0xffffffffu, v, 1);
      v += __shfl_xor_sync(0xffffffffu, v, 2);
      v += __shfl_xor_sync(0xffffffffu, v, 4);
      if (ko == 0) red[(w * 4 + bb) * 24 + r] = v;
    }
    __syncthreads();

    if (tid < 128) {
      int jpo = jj_o >> 3, jl = jj_o & 7;
      int ba0 = ((jpo * 2 + 0) * 4 + b_o) * 24 + jl * 3;
      int ba1 = ((jpo * 2 + 1) * 4 + b_o) * 24 + jl * 3;
      float sr = red[ba0 + 0] + red[ba1 + 0];
      float sz = red[ba0 + 1] + red[ba1 + 1];
      float sn = red[ba0 + 2] + red[ba1 + 2];
      float rg = sigmoid_f(xr + sr + bh[jj_o * 3 + 0]);
      float zg = sigmoid_f(xz + sz + bh[jj_o * 3 + 1]);
      float ng = tanh_f(xn + rg * (sn + bh[jj_o * 3 + 2]));
      float hnew = ng + zg * (hprev - ng);
      hn[(b0g + b_o) * HID + j0 + jj_o] = hnew;
      out[((size_t)(b0g + b_o) * SEQT + t) * HID + j0 + jj_o] = hnew;
    }
    asm volatile("barrier.cluster.arrive.aligned;" ::: "memory");
    asm volatile("barrier.cluster.wait.aligned;" ::: "memory");
  }
}

extern "C" void kernel_launch(void* const* d_in, const int* in_sizes, int n_in,
                              void* d_out, int out_size) {
  (void)in_sizes; (void)n_in; (void)out_size;
  const float* input = (const float*)d_in[0];
  const float* h0    = (const float*)d_in[1];
  const float* wih   = (const float*)d_in[2];
  const float* whh   = (const float*)d_in[3];
  const float* bih   = (const float*)d_in[4];
  const float* bhh   = (const float*)d_in[5];
  float* out = (float*)d_out;

  cudaFuncSetAttribute(gru_scan, cudaFuncAttributeMaxDynamicSharedMemorySize, SCAN_SMEM);
  cudaFuncSetAttribute(gru_scan, cudaFuncAttributeNonPortableClusterSizeAllowed, 1);

  // DIAGNOSTIC ROUND: gemm launched 5x (idempotent -> identical output).
  // T_total = 5*T_gemm + T_scan; delta vs R8 (1x) measures 4*T_gemm.
  dim3 gA(G3 / 128, (BATCH * SEQT) / 128);
  gemm_xgates<<<gA, 256>>>(input, wih, bih);
  gemm_xgates<<<gA, 256>>>(input, wih, bih);
  gemm_xgates<<<gA, 256>>>(input, wih, bih);
  gemm_xgates<<<gA, 256>>>(input, wih, bih);
  gemm_xgates<<<gA, 256>>>(input, wih, bih);
  gru_scan<<<NCLU * CLC, NT, SCAN_SMEM>>>(whh, bhh, h0, out);
}

// round 10
// speedup vs baseline: 2.1586x; 2.1586x over previous
#include <cuda_runtime.h>
#include <cstdint>
#include <cstddef>

#define BATCH 32
#define SEQT  2048
#define INSZ  512
#define HID   512
#define G3    1536
#define NT    256
#define NGRP  8
#define GSZ2  16          // CTAs per barrier group
typedef unsigned long long ull;

__device__ float g_xg[(size_t)SEQT * BATCH * G3];   // [t][b][3H]
__device__ float g_h[2][BATCH * HID];
__device__ unsigned g_bcount[NGRP][32];             // 128B-padded per group
__device__ unsigned g_bgen[NGRP][32];

// ---- packed f32x2 helpers ----
__device__ __forceinline__ ull pk2(float x, float y) {
  ull r; asm("mov.b64 %0, {%1,%2};" : "=l"(r) : "f"(x), "f"(y)); return r;
}
__device__ __forceinline__ ull ffma2(ull a, ull b, ull c) {
  ull d; asm("fma.rn.f32x2 %0, %1, %2, %3;" : "=l"(d) : "l"(a), "l"(b), "l"(c)); return d;
}
__device__ __forceinline__ float2 upk2(ull v) {
  float x, y; asm("mov.b64 {%0,%1}, %2;" : "=f"(x), "=f"(y) : "l"(v));
  return make_float2(x, y);
}
__device__ __forceinline__ float sigmoid_f(float x) { return 1.f / (1.f + __expf(-x)); }
__device__ __forceinline__ float tanh_f(float x) {
  float e = __expf(-2.f * x); return (1.f - e) / (1.f + e);
}

// =============================================================
// Kernel A: x_gates = input @ W_ih^T + b_ih  (R8/R9, measured 2.7 ms)
// =============================================================
__global__ __launch_bounds__(256, 1) void gemm_xgates(
    const float* __restrict__ A, const float* __restrict__ Wih,
    const float* __restrict__ bih) {
  __shared__ ull As2[2][8][128];
  __shared__ ull Bs2[2][8][128];

  const int tid = threadIdx.x;
  const int m0 = blockIdx.y << 7, n0 = blockIdx.x << 7;
  const int tx = tid & 15, ty = tid >> 4;
  const int lrow = tid & 127, lk4 = (tid >> 7) << 3;
  const int ty4 = ty * 4;

  const float* Ap = A + (size_t)(m0 + lrow) * INSZ + lk4;
  const float* Bp = Wih + (size_t)(n0 + lrow) * INSZ + lk4;

  ull acc[64];
#pragma unroll
  for (int i = 0; i < 64; i++) acc[i] = 0ull;

  float4 la0 = *(const float4*)(Ap), la1 = *(const float4*)(Ap + 4);
  float4 lb0 = *(const float4*)(Bp), lb1 = *(const float4*)(Bp + 4);
  {
    int kk = lk4 >> 1;
    As2[0][kk + 0][lrow] = pk2(la0.x, la0.y);
    As2[0][kk + 1][lrow] = pk2(la0.z, la0.w);
    As2[0][kk + 2][lrow] = pk2(la1.x, la1.y);
    As2[0][kk + 3][lrow] = pk2(la1.z, la1.w);
    Bs2[0][kk + 0][lrow] = pk2(lb0.x, lb0.y);
    Bs2[0][kk + 1][lrow] = pk2(lb0.z, lb0.w);
    Bs2[0][kk + 2][lrow] = pk2(lb1.x, lb1.y);
    Bs2[0][kk + 3][lrow] = pk2(lb1.z, lb1.w);
  }
  __syncthreads();

  for (int kt = 0; kt < 32; kt++) {
    const int cur = kt & 1, nxt = cur ^ 1;
    if (kt < 31) {
      Ap += 16; Bp += 16;
      la0 = *(const float4*)(Ap); la1 = *(const float4*)(Ap + 4);
      lb0 = *(const float4*)(Bp); lb1 = *(const float4*)(Bp + 4);
    }
#pragma unroll
    for (int kk = 0; kk < 8; kk++) {
      ulonglong2 aa0 = *(const ulonglong2*)&As2[cur][kk][ty4];
      ulonglong2 aa1 = *(const ulonglong2*)&As2[cur][kk][ty4 + 2];
      ulonglong2 aa2 = *(const ulonglong2*)&As2[cur][kk][64 + ty4];
      ulonglong2 aa3 = *(const ulonglong2*)&As2[cur][kk][64 + ty4 + 2];
      ulonglong2 bb0 = *(const ulonglong2*)&Bs2[cur][kk][tx * 4];
      ulonglong2 bb1 = *(const ulonglong2*)&Bs2[cur][kk][tx * 4 + 2];
      ulonglong2 bb2 = *(const ulonglong2*)&Bs2[cur][kk][64 + tx * 4];
      ulonglong2 bb3 = *(const ulonglong2*)&Bs2[cur][kk][64 + tx * 4 + 2];
      ull a2[8] = {aa0.x, aa0.y, aa1.x, aa1.y, aa2.x, aa2.y, aa3.x, aa3.y};
      ull b2[8] = {bb0.x, bb0.y, bb1.x, bb1.y, bb2.x, bb2.y, bb3.x, bb3.y};
#pragma unroll
      for (int i = 0; i < 8; i++)
#pragma unroll
        for (int j = 0; j < 8; j++)
          acc[i * 8 + j] = ffma2(a2[i], b2[j], acc[i * 8 + j]);
    }
    if (kt < 31) {
      int kk = lk4 >> 1;
      As2[nxt][kk + 0][lrow] = pk2(la0.x, la0.y);
      As2[nxt][kk + 1][lrow] = pk2(la0.z, la0.w);
      As2[nxt][kk + 2][lrow] = pk2(la1.x, la1.y);
      As2[nxt][kk + 3][lrow] = pk2(la1.z, la1.w);
      Bs2[nxt][kk + 0][lrow] = pk2(lb0.x, lb0.y);
      Bs2[nxt][kk + 1][lrow] = pk2(lb0.z, lb0.w);
      Bs2[nxt][kk + 2][lrow] = pk2(lb1.x, lb1.y);
      Bs2[nxt][kk + 3][lrow] = pk2(lb1.z, lb1.w);
    }
    __syncthreads();
  }

  float4 bia0 = *(const float4*)(bih + n0 + tx * 4);
  float4 bia1 = *(const float4*)(bih + n0 + 64 + tx * 4);
#pragma unroll
  for (int i = 0; i < 8; i++) {
    int m = m0 + ((i < 4) ? (ty4 + i) : (64 + ty4 + i - 4));
    int b = m >> 11, t = m & 2047;
    float* orow = g_xg + ((size_t)t * BATCH + b) * G3 + n0;
    float2 p; float4 o0, o1;
    p = upk2(acc[i * 8 + 0]); o0.x = p.x + p.y + bia0.x;
    p = upk2(acc[i * 8 + 1]); o0.y = p.x + p.y + bia0.y;
    p = upk2(acc[i * 8 + 2]); o0.z = p.x + p.y + bia0.z;
    p = upk2(acc[i * 8 + 3]); o0.w = p.x + p.y + bia0.w;
    p = upk2(acc[i * 8 + 4]); o1.x = p.x + p.y + bia1.x;
    p = upk2(acc[i * 8 + 5]); o1.y = p.x + p.y + bia1.y;
    p = upk2(acc[i * 8 + 6]); o1.z = p.x + p.y + bia1.z;
    p = upk2(acc[i * 8 + 7]); o1.w = p.x + p.y + bia1.w;
    *(float4*)(orow + tx * 4) = o0;
    *(float4*)(orow + 64 + tx * 4) = o1;
  }
}

// =============================================================
// Kernel B: persistent GRU scan — R6 compute body + 16-way FLAG barrier
// 8 groups x 16 CTAs; group = 4 batches; CTA = 32 hidden cols
// =============================================================
__device__ __forceinline__ void group_barrier(int grp) {
  __syncthreads();
  if (threadIdx.x == 0) {
    unsigned* cnt = &g_bcount[grp][0];
    unsigned* gen = &g_bgen[grp][0];
    unsigned g0;
    asm volatile("ld.acquire.gpu.global.u32 %0,[%1];" : "=r"(g0) : "l"(gen) : "memory");
    unsigned a;
    asm volatile("atom.add.acq_rel.gpu.global.u32 %0,[%1],1;" : "=r"(a) : "l"(cnt) : "memory");
    if (a == GSZ2 - 1) {
      asm volatile("st.relaxed.gpu.global.u32 [%0],0;" :: "l"(cnt) : "memory");
      unsigned tmp;
      asm volatile("atom.add.release.gpu.global.u32 %0,[%1],1;" : "=r"(tmp) : "l"(gen) : "memory");
    } else {
      unsigned cur;
      do {
        asm volatile("ld.acquire.gpu.global.u32 %0,[%1];" : "=r"(cur) : "l"(gen) : "memory");
      } while (cur == g0);
    }
  }
  __syncthreads();
}

#define SCAN_SMEM 208256

__global__ __launch_bounds__(NT, 1)
void gru_scan(const float* __restrict__ Whh, const float* __restrict__ bhh,
              const float* __restrict__ h0, float* __restrict__ out) {
  extern __shared__ char smem[];
  char* WS = smem;
  char* HS = smem + 196608;
  float* red = (float*)(smem + 204800);
  float* bh  = (float*)(smem + 207872);

  const int tid = threadIdx.x;
  const int grp = blockIdx.x >> 4;
  const int cid = blockIdx.x & 15;
  const int j0  = cid << 5;
  const int b0g = grp << 2;

  const int w = tid >> 5, lane = tid & 31;
  const int kh = w & 1;
  const int bb = lane >> 3, ko = lane & 7;

  for (int idx = tid; idx < 96 * 128; idx += NT) {
    int r = idx >> 7, c4 = idx & 127;
    int jj = r / 3, g = r - jj * 3;
    float4 v = *(const float4*)(Whh + (size_t)(g * HID + j0 + jj) * HID + (c4 << 2));
    int kh2 = c4 >> 6, rem = c4 & 63, ko2 = rem >> 3, s = rem & 7;
    int jp2 = jj >> 3, jl = jj & 7, rr = jl * 3 + g;
    *(float4*)(WS + ((jp2 * 2 + kh2) * 24 + rr) * 1024 + s * 128 + ko2 * 16) = v;
  }
  if (tid < 96) {
    int jj = tid / 3, g = tid - jj * 3;
    bh[tid] = bhh[g * HID + j0 + jj];
  }
  if (tid < 128) {
    int b_o = tid >> 5, jj_o = tid & 31;
    g_h[0][(b0g + b_o) * HID + j0 + jj_o] = h0[(b0g + b_o) * HID + j0 + jj_o];
  }
  group_barrier(grp);

  for (int t = 0; t < SEQT; t++) {
    const float* hp = g_h[t & 1];
    float* hn = g_h[(t + 1) & 1];

    const int b_o = tid >> 5, jj_o = tid & 31;
    float xr = 0.f, xz = 0.f, xn = 0.f, hprev = 0.f;
    if (tid < 128) {
      const float* xgp = g_xg + ((size_t)t * BATCH + (b0g + b_o)) * G3 + j0 + jj_o;
      xr = __ldcg(xgp); xz = __ldcg(xgp + HID); xn = __ldcg(xgp + 2 * HID);
      hprev = __ldcg(hp + (b0g + b_o) * HID + j0 + jj_o);
    }

#pragma unroll
    for (int i = 0; i < 2; i++) {
      int idx = i * NT + tid;
      int b_r = idx >> 7, c4 = idx & 127;
      int kh2 = c4 >> 6, rem = c4 & 63, ko2 = rem >> 3, s = rem & 7;
      const float* src = hp + (b0g + b_r) * HID + (c4 << 2);
      float4 v;
      asm volatile("ld.global.cg.v4.f32 {%0,%1,%2,%3},[%4];"
                   : "=f"(v.x), "=f"(v.y), "=f"(v.z), "=f"(v.w) : "l"(src));
      *(float4*)(HS + kh2 * 4096 + s * 512 + b_r * 128 + ko2 * 16) = v;
    }
    __syncthreads();

    ull hx[8], hy[8];
    const char* hb = HS + kh * 4096 + bb * 128 + ko * 16;
#pragma unroll
    for (int s = 0; s < 8; s++) {
      ulonglong2 u = *(const ulonglong2*)(hb + s * 512);
      hx[s] = u.x; hy[s] = u.y;
    }

    ull acc[24];
#pragma unroll
    for (int r = 0; r < 24; r++) acc[r] = 0ull;
    const char* wb = WS + (w * 24) * 1024 + ko * 16;
#pragma unroll
    for (int s = 0; s < 8; s++) {
      const char* wbs = wb + s * 128;
#pragma unroll
      for (int r = 0; r < 24; r++) {
        ulonglong2 u = *(const ulonglong2*)(wbs + r * 1024);
        acc[r] = ffma2(u.x, hx[s], acc[r]);
        acc[r] = ffma2(u.y, hy[s], acc[r]);
      }
    }

#pragma unroll
    for (int r = 0; r < 24; r++) {
      float2 p = upk2(acc[r]);
      float v = p.x + p.y;
      v += __shfl_xor_sync(0xffffffffu, v, 1);
      v += __shfl_xor_sync(0xffffffffu, v, 2);
      v += __shfl_xor_sync(0xffffffffu, v, 4);
      if (ko == 0) red[(w * 4 + bb) * 24 + r] = v;
    }
    __syncthreads();

    if (tid < 128) {
      int jpo = jj_o >> 3, jl = jj_o & 7;
      int ba0 = ((jpo * 2 + 0) * 4 + b_o) * 24 + jl * 3;
      int ba1 = ((jpo * 2 + 1) * 4 + b_o) * 24 + jl * 3;
      float sr = red[ba0 + 0] + red[ba1 + 0];
      float sz = red[ba0 + 1] + red[ba1 + 1];
      float sn = red[ba0 + 2] + red[ba1 + 2];
      float rg = sigmoid_f(xr + sr + bh[jj_o * 3 + 0]);
      float zg = sigmoid_f(xz + sz + bh[jj_o * 3 + 1]);
      float ng = tanh_f(xn + rg * (sn + bh[jj_o * 3 + 2]));
      float hnew = ng + zg * (hprev - ng);
      hn[(b0g + b_o) * HID + j0 + jj_o] = hnew;
      out[((size_t)(b0g + b_o) * SEQT + t) * HID + j0 + jj_o] = hnew;
    }
    group_barrier(grp);
  }
}

extern "C" void kernel_launch(void* const* d_in, const int* in_sizes, int n_in,
                              void* d_out, int out_size) {
  (void)in_sizes; (void)n_in; (void)out_size;
  const float* input = (const float*)d_in[0];
  const float* h0    = (const float*)d_in[1];
  const float* wih   = (const float*)d_in[2];
  const float* whh   = (const float*)d_in[3];
  const float* bih   = (const float*)d_in[4];
  const float* bhh   = (const float*)d_in[5];
  float* out = (float*)d_out;

  cudaFuncSetAttribute(gru_scan, cudaFuncAttributeMaxDynamicSharedMemorySize, SCAN_SMEM);

  dim3 gA(G3 / 128, (BATCH * SEQT) / 128);
  gemm_xgates<<<gA, 256>>>(input, wih, bih);
  gru_scan<<<NGRP * GSZ2, NT, SCAN_SMEM>>>(whh, bhh, h0, out);
}

// round 11
// speedup vs baseline: 2.7062x; 1.2537x over previous
#include <cuda_runtime.h>
#include <cstdint>
#include <cstddef>

#define BATCH 32
#define SEQT  2048
#define INSZ  512
#define HID   512
#define G3    1536
#define NT    256
#define NGRP  8
#define GSZ2  16
typedef unsigned long long ull;

__device__ float g_xg[(size_t)SEQT * BATCH * G3];   // [t][b][3H]
__device__ float g_h[2][BATCH * HID];
__device__ unsigned g_bcount[NGRP][32];
__device__ unsigned g_bgen[NGRP][32];

// ---- packed f32x2 helpers ----
__device__ __forceinline__ ull pk2(float x, float y) {
  ull r; asm("mov.b64 %0, {%1,%2};" : "=l"(r) : "f"(x), "f"(y)); return r;
}
__device__ __forceinline__ ull ffma2(ull a, ull b, ull c) {
  ull d; asm("fma.rn.f32x2 %0, %1, %2, %3;" : "=l"(d) : "l"(a), "l"(b), "l"(c)); return d;
}
__device__ __forceinline__ float2 upk2(ull v) {
  float x, y; asm("mov.b64 {%0,%1}, %2;" : "=f"(x), "=f"(y) : "l"(v));
  return make_float2(x, y);
}
__device__ __forceinline__ float sigmoid_f(float x) { return 1.f / (1.f + __expf(-x)); }
__device__ __forceinline__ float tanh_f(float x) {
  float e = __expf(-2.f * x); return (1.f - e) / (1.f + e);
}

// =============================================================
// Kernel A: x_gates GEMM (R8/R9 design, measured 2.7 ms — unchanged)
// =============================================================
__global__ __launch_bounds__(256, 1) void gemm_xgates(
    const float* __restrict__ A, const float* __restrict__ Wih,
    const float* __restrict__ bih) {
  __shared__ ull As2[2][8][128];
  __shared__ ull Bs2[2][8][128];

  const int tid = threadIdx.x;
  const int m0 = blockIdx.y << 7, n0 = blockIdx.x << 7;
  const int tx = tid & 15, ty = tid >> 4;
  const int lrow = tid & 127, lk4 = (tid >> 7) << 3;
  const int ty4 = ty * 4;

  const float* Ap = A + (size_t)(m0 + lrow) * INSZ + lk4;
  const float* Bp = Wih + (size_t)(n0 + lrow) * INSZ + lk4;

  ull acc[64];
#pragma unroll
  for (int i = 0; i < 64; i++) acc[i] = 0ull;

  float4 la0 = *(const float4*)(Ap), la1 = *(const float4*)(Ap + 4);
  float4 lb0 = *(const float4*)(Bp), lb1 = *(const float4*)(Bp + 4);
  {
    int kk = lk4 >> 1;
    As2[0][kk + 0][lrow] = pk2(la0.x, la0.y);
    As2[0][kk + 1][lrow] = pk2(la0.z, la0.w);
    As2[0][kk + 2][lrow] = pk2(la1.x, la1.y);
    As2[0][kk + 3][lrow] = pk2(la1.z, la1.w);
    Bs2[0][kk + 0][lrow] = pk2(lb0.x, lb0.y);
    Bs2[0][kk + 1][lrow] = pk2(lb0.z, lb0.w);
    Bs2[0][kk + 2][lrow] = pk2(lb1.x, lb1.y);
    Bs2[0][kk + 3][lrow] = pk2(lb1.z, lb1.w);
  }
  __syncthreads();

  for (int kt = 0; kt < 32; kt++) {
    const int cur = kt & 1, nxt = cur ^ 1;
    if (kt < 31) {
      Ap += 16; Bp += 16;
      la0 = *(const float4*)(Ap); la1 = *(const float4*)(Ap + 4);
      lb0 = *(const float4*)(Bp); lb1 = *(const float4*)(Bp + 4);
    }
#pragma unroll
    for (int kk = 0; kk < 8; kk++) {
      ulonglong2 aa0 = *(const ulonglong2*)&As2[cur][kk][ty4];
      ulonglong2 aa1 = *(const ulonglong2*)&As2[cur][kk][ty4 + 2];
      ulonglong2 aa2 = *(const ulonglong2*)&As2[cur][kk][64 + ty4];
      ulonglong2 aa3 = *(const ulonglong2*)&As2[cur][kk][64 + ty4 + 2];
      ulonglong2 bb0 = *(const ulonglong2*)&Bs2[cur][kk][tx * 4];
      ulonglong2 bb1 = *(const ulonglong2*)&Bs2[cur][kk][tx * 4 + 2];
      ulonglong2 bb2 = *(const ulonglong2*)&Bs2[cur][kk][64 + tx * 4];
      ulonglong2 bb3 = *(const ulonglong2*)&Bs2[cur][kk][64 + tx * 4 + 2];
      ull a2[8] = {aa0.x, aa0.y, aa1.x, aa1.y, aa2.x, aa2.y, aa3.x, aa3.y};
      ull b2[8] = {bb0.x, bb0.y, bb1.x, bb1.y, bb2.x, bb2.y, bb3.x, bb3.y};
#pragma unroll
      for (int i = 0; i < 8; i++)
#pragma unroll
        for (int j = 0; j < 8; j++)
          acc[i * 8 + j] = ffma2(a2[i], b2[j], acc[i * 8 + j]);
    }
    if (kt < 31) {
      int kk = lk4 >> 1;
      As2[nxt][kk + 0][lrow] = pk2(la0.x, la0.y);
      As2[nxt][kk + 1][lrow] = pk2(la0.z, la0.w);
      As2[nxt][kk + 2][lrow] = pk2(la1.x, la1.y);
      As2[nxt][kk + 3][lrow] = pk2(la1.z, la1.w);
      Bs2[nxt][kk + 0][lrow] = pk2(lb0.x, lb0.y);
      Bs2[nxt][kk + 1][lrow] = pk2(lb0.z, lb0.w);
      Bs2[nxt][kk + 2][lrow] = pk2(lb1.x, lb1.y);
      Bs2[nxt][kk + 3][lrow] = pk2(lb1.z, lb1.w);
    }
    __syncthreads();
  }

  float4 bia0 = *(const float4*)(bih + n0 + tx * 4);
  float4 bia1 = *(const float4*)(bih + n0 + 64 + tx * 4);
#pragma unroll
  for (int i = 0; i < 8; i++) {
    int m = m0 + ((i < 4) ? (ty4 + i) : (64 + ty4 + i - 4));
    int b = m >> 11, t = m & 2047;
    float* orow = g_xg + ((size_t)t * BATCH + b) * G3 + n0;
    float2 p; float4 o0, o1;
    p = upk2(acc[i * 8 + 0]); o0.x = p.x + p.y + bia0.x;
    p = upk2(acc[i * 8 + 1]); o0.y = p.x + p.y + bia0.y;
    p = upk2(acc[i * 8 + 2]); o0.z = p.x + p.y + bia0.z;
    p = upk2(acc[i * 8 + 3]); o0.w = p.x + p.y + bia0.w;
    p = upk2(acc[i * 8 + 4]); o1.x = p.x + p.y + bia1.x;
    p = upk2(acc[i * 8 + 5]); o1.y = p.x + p.y + bia1.y;
    p = upk2(acc[i * 8 + 6]); o1.z = p.x + p.y + bia1.z;
    p = upk2(acc[i * 8 + 7]); o1.w = p.x + p.y + bia1.w;
    *(float4*)(orow + tx * 4) = o0;
    *(float4*)(orow + 64 + tx * 4) = o1;
  }
}

// =============================================================
// Kernel B: persistent GRU scan — lane-owns-k, batch reuse in regs
// 8 groups x 16 CTAs; group = 4 batches; CTA = 32 hidden cols
// Lane = k-segment [lane*16, lane*16+16); warp = 12 rows (4j x 3g)
// smem: WS 192KB @0 | HS 8KB @196608 | red 12KB @204800 | bh @217088
// =============================================================
__device__ __forceinline__ void group_barrier(int grp) {
  __syncthreads();
  if (threadIdx.x == 0) {
    unsigned* cnt = &g_bcount[grp][0];
    unsigned* gen = &g_bgen[grp][0];
    unsigned g0;
    asm volatile("ld.acquire.gpu.global.u32 %0,[%1];" : "=r"(g0) : "l"(gen) : "memory");
    unsigned a;
    asm volatile("atom.add.acq_rel.gpu.global.u32 %0,[%1],1;" : "=r"(a) : "l"(cnt) : "memory");
    if (a == GSZ2 - 1) {
      asm volatile("st.relaxed.gpu.global.u32 [%0],0;" :: "l"(cnt) : "memory");
      unsigned tmp;
      asm volatile("atom.add.release.gpu.global.u32 %0,[%1],1;" : "=r"(tmp) : "l"(gen) : "memory");
    } else {
      unsigned cur;
      do {
        asm volatile("ld.acquire.gpu.global.u32 %0,[%1];" : "=r"(cur) : "l"(gen) : "memory");
      } while (cur == g0);
    }
  }
  __syncthreads();
}

#define SCAN_SMEM 217472

__global__ __launch_bounds__(NT, 1)
void gru_scan(const float* __restrict__ Whh, const float* __restrict__ bhh,
              const float* __restrict__ h0, float* __restrict__ out) {
  extern __shared__ char smem[];
  char* WS = smem;                      // row R: [i 0..3][lane 0..31][16B]
  char* HS = smem + 196608;             // [b][i][lane][16B]
  float* red = (float*)(smem + 204800); // [w][rb 48][8 partials]
  float* bh  = (float*)(smem + 217088); // [96] = [jj*3+g]

  const int tid = threadIdx.x;
  const int grp = blockIdx.x >> 4;
  const int cid = blockIdx.x & 15;
  const int j0  = cid << 5;
  const int b0g = grp << 2;
  const int w = tid >> 5, lane = tid & 31;

  // --- stage W: row R = jj*3+g <-> Whh row g*512 + j0+jj ---
  // float4 c4 (k=c4*4): i = c4&3, l = c4>>2 -> off = R*2048 + i*512 + l*16
  for (int idx = tid; idx < 96 * 128; idx += NT) {
    int R = idx >> 7, c4 = idx & 127;
    int jj = R / 3, g = R - jj * 3;
    float4 v = *(const float4*)(Whh + (size_t)(g * HID + j0 + jj) * HID + (c4 << 2));
    *(float4*)(WS + R * 2048 + (c4 & 3) * 512 + (c4 >> 2) * 16) = v;
  }
  if (tid < 96) {
    int jj = tid / 3, g = tid - jj * 3;
    bh[tid] = bhh[g * HID + j0 + jj];
  }
  if (tid < 128) {
    int b_o = tid >> 5, jj_o = tid & 31;
    g_h[0][(b0g + b_o) * HID + j0 + jj_o] = h0[(b0g + b_o) * HID + j0 + jj_o];
  }
  group_barrier(grp);

  const int b_o = tid >> 5, jj_o = tid & 31;

  for (int t = 0; t < SEQT; t++) {
    const float* hp = g_h[t & 1];
    float* hn = g_h[(t + 1) & 1];

    // prefetch per-output operands (threads 0..127)
    float xr = 0.f, xz = 0.f, xn = 0.f, hprev = 0.f;
    if (tid < 128) {
      const float* xgp = g_xg + ((size_t)t * BATCH + (b0g + b_o)) * G3 + j0 + jj_o;
      xr = __ldcg(xgp); xz = __ldcg(xgp + HID); xn = __ldcg(xgp + 2 * HID);
      hprev = __ldcg(hp + (b0g + b_o) * HID + j0 + jj_o);
    }

    // --- stage group h (8KB): chunk (b, c4) -> b*2048 + (c4&3)*512 + (c4>>2)*16
#pragma unroll
    for (int i = 0; i < 2; i++) {
      int idx = i * NT + tid;                 // 0..511
      int b_r = idx >> 7, c4 = idx & 127;
      const float* src = hp + (b0g + b_r) * HID + (c4 << 2);
      float4 v;
      asm volatile("ld.global.cg.v4.f32 {%0,%1,%2,%3},[%4];"
                   : "=f"(v.x), "=f"(v.y), "=f"(v.z), "=f"(v.w) : "l"(src));
      *(float4*)(HS + b_r * 2048 + (c4 & 3) * 512 + (c4 >> 2) * 16) = v;
    }
    __syncthreads();

    // --- preload lane's h: 4 batches x 16 k (fully-unique LDS.128) ---
    ull hreg[4][8];
#pragma unroll
    for (int b = 0; b < 4; b++) {
      const char* hb = HS + b * 2048 + lane * 16;
#pragma unroll
      for (int i = 0; i < 4; i++) {
        ulonglong2 u = *(const ulonglong2*)(hb + i * 512);
        hreg[b][i * 2] = u.x; hreg[b][i * 2 + 1] = u.y;
      }
    }

    // --- 12 rows x 4 batches x 16 k per lane (W reuse across batches) ---
    ull acc[48];
#pragma unroll
    for (int c = 0; c < 48; c++) acc[c] = 0ull;
#pragma unroll
    for (int rl = 0; rl < 12; rl++) {
      const char* wrow = WS + (w * 12 + rl) * 2048 + lane * 16;
      ull wu[8];
#pragma unroll
      for (int i = 0; i < 4; i++) {
        ulonglong2 u = *(const ulonglong2*)(wrow + i * 512);
        wu[i * 2] = u.x; wu[i * 2 + 1] = u.y;
      }
#pragma unroll
      for (int b = 0; b < 4; b++) {
        ull s = acc[rl * 4 + b];
#pragma unroll
        for (int u = 0; u < 8; u++) s = ffma2(wu[u], hreg[b][u], s);
        acc[rl * 4 + b] = s;
      }
    }

    // --- reduce: x+y, then xor16+xor8 -> 8 partials -> smem ---
#pragma unroll
    for (int c = 0; c < 48; c++) {
      float2 p = upk2(acc[c]);
      float v = p.x + p.y;
      v += __shfl_xor_sync(0xffffffffu, v, 16);
      v += __shfl_xor_sync(0xffffffffu, v, 8);
      if (lane < 8) red[w * 384 + c * 8 + lane] = v;
    }
    __syncthreads();

    // --- gate math (threads 0..127: one (b, j) each) ---
    if (tid < 128) {
      int wj = jj_o >> 2, jl = jj_o & 3;
      const float* rp = red + wj * 384 + b_o * 8;
      float sr = 0.f, sz = 0.f, sn = 0.f;
#pragma unroll
      for (int p = 0; p < 8; p++) {
        sr += rp[(jl * 3 + 0) * 32 + p];
        sz += rp[(jl * 3 + 1) * 32 + p];
        sn += rp[(jl * 3 + 2) * 32 + p];
      }
      float rg = sigmoid_f(xr + sr + bh[jj_o * 3 + 0]);
      float zg = sigmoid_f(xz + sz + bh[jj_o * 3 + 1]);
      float ng = tanh_f(xn + rg * (sn + bh[jj_o * 3 + 2]));
      float hnew = ng + zg * (hprev - ng);
      hn[(b0g + b_o) * HID + j0 + jj_o] = hnew;
      out[((size_t)(b0g + b_o) * SEQT + t) * HID + j0 + jj_o] = hnew;
    }
    group_barrier(grp);
  }
}

extern "C" void kernel_launch(void* const* d_in, const int* in_sizes, int n_in,
                              void* d_out, int out_size) {
  (void)in_sizes; (void)n_in; (void)out_size;
  const float* input = (const float*)d_in[0];
  const float* h0    = (const float*)d_in[1];
  const float* wih   = (const float*)d_in[2];
  const float* whh   = (const float*)d_in[3];
  const float* bih   = (const float*)d_in[4];
  const float* bhh   = (const float*)d_in[5];
  float* out = (float*)d_out;

  cudaFuncSetAttribute(gru_scan, cudaFuncAttributeMaxDynamicSharedMemorySize, SCAN_SMEM);

  dim3 gA(G3 / 128, (BATCH * SEQT) / 128);
  gemm_xgates<<<gA, 256>>>(input, wih, bih);
  gru_scan<<<NGRP * GSZ2, NT, SCAN_SMEM>>>(whh, bhh, h0, out);
}

// round 12
// speedup vs baseline: 3.0625x; 1.1316x over previous
#include <cuda_runtime.h>
#include <cstdint>
#include <cstddef>

#define BATCH 32
#define SEQT  2048
#define INSZ  512
#define HID   512
#define G3    1536
#define NT    256
#define NGRP  8
#define GSZ2  16
typedef unsigned long long ull;

__device__ float g_xg[(size_t)SEQT * BATCH * G3];   // [t][b][3H]
__device__ float g_h[2][BATCH * HID];
__device__ unsigned g_flags[128][32];               // per-CTA step flag, 128B stride
__device__ unsigned g_bcount[NGRP][32];             // one-time init barrier (ends at 0)
__device__ unsigned g_bgen[NGRP][32];

// ---- packed f32x2 helpers ----
__device__ __forceinline__ ull pk2(float x, float y) {
  ull r; asm("mov.b64 %0, {%1,%2};" : "=l"(r) : "f"(x), "f"(y)); return r;
}
__device__ __forceinline__ ull ffma2(ull a, ull b, ull c) {
  ull d; asm("fma.rn.f32x2 %0, %1, %2, %3;" : "=l"(d) : "l"(a), "l"(b), "l"(c)); return d;
}
__device__ __forceinline__ float2 upk2(ull v) {
  float x, y; asm("mov.b64 {%0,%1}, %2;" : "=f"(x), "=f"(y) : "l"(v));
  return make_float2(x, y);
}
__device__ __forceinline__ float sigmoid_f(float x) { return 1.f / (1.f + __expf(-x)); }
__device__ __forceinline__ float tanh_f(float x) {
  float e = __expf(-2.f * x); return (1.f - e) / (1.f + e);
}

// =============================================================
// Kernel A: x_gates GEMM (measured 2.7 ms — unchanged)
// =============================================================
__global__ __launch_bounds__(256, 1) void gemm_xgates(
    const float* __restrict__ A, const float* __restrict__ Wih,
    const float* __restrict__ bih) {
  __shared__ ull As2[2][8][128];
  __shared__ ull Bs2[2][8][128];

  const int tid = threadIdx.x;
  const int m0 = blockIdx.y << 7, n0 = blockIdx.x << 7;
  const int tx = tid & 15, ty = tid >> 4;
  const int lrow = tid & 127, lk4 = (tid >> 7) << 3;
  const int ty4 = ty * 4;

  const float* Ap = A + (size_t)(m0 + lrow) * INSZ + lk4;
  const float* Bp = Wih + (size_t)(n0 + lrow) * INSZ + lk4;

  ull acc[64];
#pragma unroll
  for (int i = 0; i < 64; i++) acc[i] = 0ull;

  float4 la0 = *(const float4*)(Ap), la1 = *(const float4*)(Ap + 4);
  float4 lb0 = *(const float4*)(Bp), lb1 = *(const float4*)(Bp + 4);
  {
    int kk = lk4 >> 1;
    As2[0][kk + 0][lrow] = pk2(la0.x, la0.y);
    As2[0][kk + 1][lrow] = pk2(la0.z, la0.w);
    As2[0][kk + 2][lrow] = pk2(la1.x, la1.y);
    As2[0][kk + 3][lrow] = pk2(la1.z, la1.w);
    Bs2[0][kk + 0][lrow] = pk2(lb0.x, lb0.y);
    Bs2[0][kk + 1][lrow] = pk2(lb0.z, lb0.w);
    Bs2[0][kk + 2][lrow] = pk2(lb1.x, lb1.y);
    Bs2[0][kk + 3][lrow] = pk2(lb1.z, lb1.w);
  }
  __syncthreads();

  for (int kt = 0; kt < 32; kt++) {
    const int cur = kt & 1, nxt = cur ^ 1;
    if (kt < 31) {
      Ap += 16; Bp += 16;
      la0 = *(const float4*)(Ap); la1 = *(const float4*)(Ap + 4);
      lb0 = *(const float4*)(Bp); lb1 = *(const float4*)(Bp + 4);
    }
#pragma unroll
    for (int kk = 0; kk < 8; kk++) {
      ulonglong2 aa0 = *(const ulonglong2*)&As2[cur][kk][ty4];
      ulonglong2 aa1 = *(const ulonglong2*)&As2[cur][kk][ty4 + 2];
      ulonglong2 aa2 = *(const ulonglong2*)&As2[cur][kk][64 + ty4];
      ulonglong2 aa3 = *(const ulonglong2*)&As2[cur][kk][64 + ty4 + 2];
      ulonglong2 bb0 = *(const ulonglong2*)&Bs2[cur][kk][tx * 4];
      ulonglong2 bb1 = *(const ulonglong2*)&Bs2[cur][kk][tx * 4 + 2];
      ulonglong2 bb2 = *(const ulonglong2*)&Bs2[cur][kk][64 + tx * 4];
      ulonglong2 bb3 = *(const ulonglong2*)&Bs2[cur][kk][64 + tx * 4 + 2];
      ull a2[8] = {aa0.x, aa0.y, aa1.x, aa1.y, aa2.x, aa2.y, aa3.x, aa3.y};
      ull b2[8] = {bb0.x, bb0.y, bb1.x, bb1.y, bb2.x, bb2.y, bb3.x, bb3.y};
#pragma unroll
      for (int i = 0; i < 8; i++)
#pragma unroll
        for (int j = 0; j < 8; j++)
          acc[i * 8 + j] = ffma2(a2[i], b2[j], acc[i * 8 + j]);
    }
    if (kt < 31) {
      int kk = lk4 >> 1;
      As2[nxt][kk + 0][lrow] = pk2(la0.x, la0.y);
      As2[nxt][kk + 1][lrow] = pk2(la0.z, la0.w);
      As2[nxt][kk + 2][lrow] = pk2(la1.x, la1.y);
      As2[nxt][kk + 3][lrow] = pk2(la1.z, la1.w);
      Bs2[nxt][kk + 0][lrow] = pk2(lb0.x, lb0.y);
      Bs2[nxt][kk + 1][lrow] = pk2(lb0.z, lb0.w);
      Bs2[nxt][kk + 2][lrow] = pk2(lb1.x, lb1.y);
      Bs2[nxt][kk + 3][lrow] = pk2(lb1.z, lb1.w);
    }
    __syncthreads();
  }

  float4 bia0 = *(const float4*)(bih + n0 + tx * 4);
  float4 bia1 = *(const float4*)(bih + n0 + 64 + tx * 4);
#pragma unroll
  for (int i = 0; i < 8; i++) {
    int m = m0 + ((i < 4) ? (ty4 + i) : (64 + ty4 + i - 4));
    int b = m >> 11, t = m & 2047;
    float* orow = g_xg + ((size_t)t * BATCH + b) * G3 + n0;
    float2 p; float4 o0, o1;
    p = upk2(acc[i * 8 + 0]); o0.x = p.x + p.y + bia0.x;
    p = upk2(acc[i * 8 + 1]); o0.y = p.x + p.y + bia0.y;
    p = upk2(acc[i * 8 + 2]); o0.z = p.x + p.y + bia0.z;
    p = upk2(acc[i * 8 + 3]); o0.w = p.x + p.y + bia0.w;
    p = upk2(acc[i * 8 + 4]); o1.x = p.x + p.y + bia1.x;
    p = upk2(acc[i * 8 + 5]); o1.y = p.x + p.y + bia1.y;
    p = upk2(acc[i * 8 + 6]); o1.z = p.x + p.y + bia1.z;
    p = upk2(acc[i * 8 + 7]); o1.w = p.x + p.y + bia1.w;
    *(float4*)(orow + tx * 4) = o0;
    *(float4*)(orow + 64 + tx * 4) = o1;
  }
}

// =============================================================
// Kernel B: persistent GRU scan — flag sync + direct-L2 h + plain W rows
// 8 groups x 16 CTAs; group = 4 batches; CTA = 32 cols; warp = 12 rows
// Lane owns k in {4*lane + 128*i, i=0..3} (coalesced LDG + conflict-free LDS)
// smem: WS 192KB @0 | red 12KB @196608 | bh @208896
// =============================================================
__device__ __forceinline__ void init_barrier(int grp) {
  __syncthreads();
  if (threadIdx.x == 0) {
    unsigned* cnt = &g_bcount[grp][0];
    unsigned* gen = &g_bgen[grp][0];
    unsigned g0;
    asm volatile("ld.acquire.gpu.global.u32 %0,[%1];" : "=r"(g0) : "l"(gen) : "memory");
    unsigned a;
    asm volatile("atom.add.acq_rel.gpu.global.u32 %0,[%1],1;" : "=r"(a) : "l"(cnt) : "memory");
    if (a == GSZ2 - 1) {
      asm volatile("st.relaxed.gpu.global.u32 [%0],0;" :: "l"(cnt) : "memory");
      unsigned tmp;
      asm volatile("atom.add.release.gpu.global.u32 %0,[%1],1;" : "=r"(tmp) : "l"(gen) : "memory");
    } else {
      unsigned cur;
      do {
        asm volatile("ld.acquire.gpu.global.u32 %0,[%1];" : "=r"(cur) : "l"(gen) : "memory");
      } while (cur == g0);
    }
  }
  __syncthreads();
}

#define SCAN_SMEM 209280

__global__ __launch_bounds__(NT, 1)
void gru_scan(const float* __restrict__ Whh, const float* __restrict__ bhh,
              const float* __restrict__ h0, float* __restrict__ out) {
  extern __shared__ char smem[];
  char* WS = smem;                      // 96 rows x 2048B, plain row-major
  float* red = (float*)(smem + 196608); // [w][48 vals][8 partials]
  float* bh  = (float*)(smem + 208896); // [96] = [jj*3+g]

  const int tid = threadIdx.x;
  const int grp = (int)blockIdx.x >> 4;
  const int cid = (int)blockIdx.x & 15;
  const int j0  = cid << 5;
  const int b0g = grp << 2;
  const int w = tid >> 5, lane = tid & 31;

  // --- stage W rows plainly: smem row R = jj*3+g <- Whh row g*512 + j0+jj ---
  for (int idx = tid; idx < 96 * 128; idx += NT) {
    int R = idx >> 7, c4 = idx & 127;
    int jj = R / 3, g = R - jj * 3;
    *(float4*)(WS + R * 2048 + c4 * 16) =
        *(const float4*)(Whh + (size_t)(g * HID + j0 + jj) * HID + (c4 << 2));
  }
  if (tid < 96) {
    int jj = tid / 3, g = tid - jj * 3;
    bh[tid] = bhh[g * HID + j0 + jj];
  }
  if (tid == 0) g_flags[blockIdx.x][0] = 0u;   // clear stale replay value
  init_barrier(grp);                            // one-time; counters end at 0

  const int b_o = tid >> 5, jj_o = tid & 31;

  for (int t = 0; t < SEQT; t++) {
    const float* hsrc = (t == 0) ? h0 : &g_h[t & 1][0];
    float* hn = &g_h[(t + 1) & 1][0];

    // xg prefetch (independent of flags)
    float xr = 0.f, xz = 0.f, xn = 0.f;
    if (tid < 128) {
      const float* xgp = g_xg + ((size_t)t * BATCH + (b0g + b_o)) * G3 + j0 + jj_o;
      xr = __ldcg(xgp); xz = __ldcg(xgp + HID); xn = __ldcg(xgp + 2 * HID);
    }

    // wait for all group producers of h_t (skip at t=0: h0 is an input)
    if (t > 0) {
      if (tid < 16) {
        const unsigned* fp = &g_flags[grp * 16 + tid][0];
        unsigned v;
        do {
          asm volatile("ld.acquire.gpu.global.u32 %0,[%1];" : "=r"(v) : "l"(fp) : "memory");
        } while (v < (unsigned)t);
      }
      __syncthreads();
    }

    float hprev = 0.f;
    if (tid < 128) hprev = __ldcg(hsrc + (b0g + b_o) * HID + j0 + jj_o);

    // --- h direct from L2: lane's k = {4*lane + 128*i}; fully coalesced ---
    ull hreg[4][8];
#pragma unroll
    for (int b = 0; b < 4; b++) {
      const float* hb = hsrc + (b0g + b) * HID + lane * 4;
#pragma unroll
      for (int i = 0; i < 4; i++) {
        float4 v;
        asm volatile("ld.global.cg.v4.f32 {%0,%1,%2,%3},[%4];"
                     : "=f"(v.x), "=f"(v.y), "=f"(v.z), "=f"(v.w)
                     : "l"(hb + i * 128));
        hreg[b][i * 2] = pk2(v.x, v.y);
        hreg[b][i * 2 + 1] = pk2(v.z, v.w);
      }
    }

    // --- 12 rows x 4 batches x 16 k per lane; W LDS fully unique ---
    ull acc[48];
#pragma unroll
    for (int c = 0; c < 48; c++) acc[c] = 0ull;
#pragma unroll
    for (int rl = 0; rl < 12; rl++) {
      const char* wrow = WS + (w * 12 + rl) * 2048 + lane * 16;
      ull wu[8];
#pragma unroll
      for (int i = 0; i < 4; i++) {
        ulonglong2 u = *(const ulonglong2*)(wrow + i * 512);
        wu[i * 2] = u.x; wu[i * 2 + 1] = u.y;
      }
#pragma unroll
      for (int b = 0; b < 4; b++) {
        ull s = acc[rl * 4 + b];
#pragma unroll
        for (int u = 0; u < 8; u++) s = ffma2(wu[u], hreg[b][u], s);
        acc[rl * 4 + b] = s;
      }
    }

    // --- reduce: x+y, xor16, xor8 -> 8 partials -> smem ---
#pragma unroll
    for (int c = 0; c < 48; c++) {
      float2 p = upk2(acc[c]);
      float v = p.x + p.y;
      v += __shfl_xor_sync(0xffffffffu, v, 16);
      v += __shfl_xor_sync(0xffffffffu, v, 8);
      if (lane < 8) red[w * 384 + c * 8 + lane] = v;
    }
    __syncthreads();

    // --- gate math (threads 0..127) ---
    if (tid < 128) {
      int wj = jj_o >> 2, jl = jj_o & 3;
      const float* rp = red + wj * 384 + b_o * 8;
      float sr = 0.f, sz = 0.f, sn = 0.f;
#pragma unroll
      for (int p = 0; p < 8; p++) {
        sr += rp[(jl * 3 + 0) * 32 + p];
        sz += rp[(jl * 3 + 1) * 32 + p];
        sn += rp[(jl * 3 + 2) * 32 + p];
      }
      float rg = sigmoid_f(xr + sr + bh[jj_o * 3 + 0]);
      float zg = sigmoid_f(xz + sz + bh[jj_o * 3 + 1]);
      float ng = tanh_f(xn + rg * (sn + bh[jj_o * 3 + 2]));
      float hnew = ng + zg * (hprev - ng);
      hn[(b0g + b_o) * HID + j0 + jj_o] = hnew;
      out[((size_t)(b0g + b_o) * SEQT + t) * HID + j0 + jj_o] = hnew;
    }
    __syncthreads();   // all h stores done
    if (tid == 0) {
      unsigned* fp = &g_flags[blockIdx.x][0];
      asm volatile("st.release.gpu.global.u32 [%0],%1;" :: "l"(fp), "r"((unsigned)(t + 1)) : "memory");
    }
  }
}

extern "C" void kernel_launch(void* const* d_in, const int* in_sizes, int n_in,
                              void* d_out, int out_size) {
  (void)in_sizes; (void)n_in; (void)out_size;
  const float* input = (const float*)d_in[0];
  const float* h0    = (const float*)d_in[1];
  const float* wih   = (const float*)d_in[2];
  const float* whh   = (const float*)d_in[3];
  const float* bih   = (const float*)d_in[4];
  const float* bhh   = (const float*)d_in[5];
  float* out = (float*)d_out;

  cudaFuncSetAttribute(gru_scan, cudaFuncAttributeMaxDynamicSharedMemorySize, SCAN_SMEM);

  dim3 gA(G3 / 128, (BATCH * SEQT) / 128);
  gemm_xgates<<<gA, 256>>>(input, wih, bih);
  gru_scan<<<NGRP * GSZ2, NT, SCAN_SMEM>>>(whh, bhh, h0, out);
}

// round 13
// speedup vs baseline: 3.1178x; 1.0181x over previous
#include <cuda_runtime.h>
#include <cstdint>
#include <cstddef>

#define BATCH 32
#define SEQT  2048
#define INSZ  512
#define HID   512
#define G3    1536
#define NT    256
#define NGRP  8
#define GSZ2  16
typedef unsigned long long ull;

__device__ float g_xg[(size_t)SEQT * BATCH * G3];   // [t][b][3H]
__device__ float g_h[2][BATCH * HID];
__device__ unsigned g_flags[128][32];               // per-CTA step flag, 128B stride
__device__ unsigned g_bcount[NGRP][32];             // one-time init barrier (ends at 0)
__device__ unsigned g_bgen[NGRP][32];

// ---- packed f32x2 helpers ----
__device__ __forceinline__ ull pk2(float x, float y) {
  ull r; asm("mov.b64 %0, {%1,%2};" : "=l"(r) : "f"(x), "f"(y)); return r;
}
__device__ __forceinline__ ull ffma2(ull a, ull b, ull c) {
  ull d; asm("fma.rn.f32x2 %0, %1, %2, %3;" : "=l"(d) : "l"(a), "l"(b), "l"(c)); return d;
}
__device__ __forceinline__ float2 upk2(ull v) {
  float x, y; asm("mov.b64 {%0,%1}, %2;" : "=f"(x), "=f"(y) : "l"(v));
  return make_float2(x, y);
}
__device__ __forceinline__ float sigmoid_f(float x) { return 1.f / (1.f + __expf(-x)); }
__device__ __forceinline__ float tanh_f(float x) {
  float e = __expf(-2.f * x); return (1.f - e) / (1.f + e);
}

// =============================================================
// Kernel A: x_gates GEMM (measured 2.7 ms — unchanged)
// =============================================================
__global__ __launch_bounds__(256, 1) void gemm_xgates(
    const float* __restrict__ A, const float* __restrict__ Wih,
    const float* __restrict__ bih) {
  __shared__ ull As2[2][8][128];
  __shared__ ull Bs2[2][8][128];

  const int tid = threadIdx.x;
  const int m0 = blockIdx.y << 7, n0 = blockIdx.x << 7;
  const int tx = tid & 15, ty = tid >> 4;
  const int lrow = tid & 127, lk4 = (tid >> 7) << 3;
  const int ty4 = ty * 4;

  const float* Ap = A + (size_t)(m0 + lrow) * INSZ + lk4;
  const float* Bp = Wih + (size_t)(n0 + lrow) * INSZ + lk4;

  ull acc[64];
#pragma unroll
  for (int i = 0; i < 64; i++) acc[i] = 0ull;

  float4 la0 = *(const float4*)(Ap), la1 = *(const float4*)(Ap + 4);
  float4 lb0 = *(const float4*)(Bp), lb1 = *(const float4*)(Bp + 4);
  {
    int kk = lk4 >> 1;
    As2[0][kk + 0][lrow] = pk2(la0.x, la0.y);
    As2[0][kk + 1][lrow] = pk2(la0.z, la0.w);
    As2[0][kk + 2][lrow] = pk2(la1.x, la1.y);
    As2[0][kk + 3][lrow] = pk2(la1.z, la1.w);
    Bs2[0][kk + 0][lrow] = pk2(lb0.x, lb0.y);
    Bs2[0][kk + 1][lrow] = pk2(lb0.z, lb0.w);
    Bs2[0][kk + 2][lrow] = pk2(lb1.x, lb1.y);
    Bs2[0][kk + 3][lrow] = pk2(lb1.z, lb1.w);
  }
  __syncthreads();

  for (int kt = 0; kt < 32; kt++) {
    const int cur = kt & 1, nxt = cur ^ 1;
    if (kt < 31) {
      Ap += 16; Bp += 16;
      la0 = *(const float4*)(Ap); la1 = *(const float4*)(Ap + 4);
      lb0 = *(const float4*)(Bp); lb1 = *(const float4*)(Bp + 4);
    }
#pragma unroll
    for (int kk = 0; kk < 8; kk++) {
      ulonglong2 aa0 = *(const ulonglong2*)&As2[cur][kk][ty4];
      ulonglong2 aa1 = *(const ulonglong2*)&As2[cur][kk][ty4 + 2];
      ulonglong2 aa2 = *(const ulonglong2*)&As2[cur][kk][64 + ty4];
      ulonglong2 aa3 = *(const ulonglong2*)&As2[cur][kk][64 + ty4 + 2];
      ulonglong2 bb0 = *(const ulonglong2*)&Bs2[cur][kk][tx * 4];
      ulonglong2 bb1 = *(const ulonglong2*)&Bs2[cur][kk][tx * 4 + 2];
      ulonglong2 bb2 = *(const ulonglong2*)&Bs2[cur][kk][64 + tx * 4];
      ulonglong2 bb3 = *(const ulonglong2*)&Bs2[cur][kk][64 + tx * 4 + 2];
      ull a2[8] = {aa0.x, aa0.y, aa1.x, aa1.y, aa2.x, aa2.y, aa3.x, aa3.y};
      ull b2[8] = {bb0.x, bb0.y, bb1.x, bb1.y, bb2.x, bb2.y, bb3.x, bb3.y};
#pragma unroll
      for (int i = 0; i < 8; i++)
#pragma unroll
        for (int j = 0; j < 8; j++)
          acc[i * 8 + j] = ffma2(a2[i], b2[j], acc[i * 8 + j]);
    }
    if (kt < 31) {
      int kk = lk4 >> 1;
      As2[nxt][kk + 0][lrow] = pk2(la0.x, la0.y);
      As2[nxt][kk + 1][lrow] = pk2(la0.z, la0.w);
      As2[nxt][kk + 2][lrow] = pk2(la1.x, la1.y);
      As2[nxt][kk + 3][lrow] = pk2(la1.z, la1.w);
      Bs2[nxt][kk + 0][lrow] = pk2(lb0.x, lb0.y);
      Bs2[nxt][kk + 1][lrow] = pk2(lb0.z, lb0.w);
      Bs2[nxt][kk + 2][lrow] = pk2(lb1.x, lb1.y);
      Bs2[nxt][kk + 3][lrow] = pk2(lb1.z, lb1.w);
    }
    __syncthreads();
  }

  float4 bia0 = *(const float4*)(bih + n0 + tx * 4);
  float4 bia1 = *(const float4*)(bih + n0 + 64 + tx * 4);
#pragma unroll
  for (int i = 0; i < 8; i++) {
    int m = m0 + ((i < 4) ? (ty4 + i) : (64 + ty4 + i - 4));
    int b = m >> 11, t = m & 2047;
    float* orow = g_xg + ((size_t)t * BATCH + b) * G3 + n0;
    float2 p; float4 o0, o1;
    p = upk2(acc[i * 8 + 0]); o0.x = p.x + p.y + bia0.x;
    p = upk2(acc[i * 8 + 1]); o0.y = p.x + p.y + bia0.y;
    p = upk2(acc[i * 8 + 2]); o0.z = p.x + p.y + bia0.z;
    p = upk2(acc[i * 8 + 3]); o0.w = p.x + p.y + bia0.w;
    p = upk2(acc[i * 8 + 4]); o1.x = p.x + p.y + bia1.x;
    p = upk2(acc[i * 8 + 5]); o1.y = p.x + p.y + bia1.y;
    p = upk2(acc[i * 8 + 6]); o1.z = p.x + p.y + bia1.z;
    p = upk2(acc[i * 8 + 7]); o1.w = p.x + p.y + bia1.w;
    *(float4*)(orow + tx * 4) = o0;
    *(float4*)(orow + 64 + tx * 4) = o1;
  }
}

// =============================================================
// Kernel B: persistent GRU scan — flag sync + SMEM-staged h (unique LDS)
// 8 groups x 16 CTAs; group = 4 batches; CTA = 32 cols; warp = 12 rows
// Lane owns k in {4*lane + 128*i, i=0..3}
// smem: WS 192KB @0 | HS 8KB @196608 | red 12KB @204800 | bh @217088
// =============================================================
__device__ __forceinline__ void init_barrier(int grp) {
  __syncthreads();
  if (threadIdx.x == 0) {
    unsigned* cnt = &g_bcount[grp][0];
    unsigned* gen = &g_bgen[grp][0];
    unsigned g0;
    asm volatile("ld.acquire.gpu.global.u32 %0,[%1];" : "=r"(g0) : "l"(gen) : "memory");
    unsigned a;
    asm volatile("atom.add.acq_rel.gpu.global.u32 %0,[%1],1;" : "=r"(a) : "l"(cnt) : "memory");
    if (a == GSZ2 - 1) {
      asm volatile("st.relaxed.gpu.global.u32 [%0],0;" :: "l"(cnt) : "memory");
      unsigned tmp;
      asm volatile("atom.add.release.gpu.global.u32 %0,[%1],1;" : "=r"(tmp) : "l"(gen) : "memory");
    } else {
      unsigned cur;
      do {
        asm volatile("ld.acquire.gpu.global.u32 %0,[%1];" : "=r"(cur) : "l"(gen) : "memory");
      } while (cur == g0);
    }
  }
  __syncthreads();
}

#define SCAN_SMEM 217472

__global__ __launch_bounds__(NT, 1)
void gru_scan(const float* __restrict__ Whh, const float* __restrict__ bhh,
              const float* __restrict__ h0, float* __restrict__ out) {
  extern __shared__ char smem[];
  char* WS = smem;                      // 96 rows x 2048B, plain row-major
  char* HS = smem + 196608;             // [b][512 cols], plain row-major, 8KB
  float* red = (float*)(smem + 204800); // [w][48 vals][8 partials]
  float* bh  = (float*)(smem + 217088); // [96] = [jj*3+g]

  const int tid = threadIdx.x;
  const int grp = (int)blockIdx.x >> 4;
  const int cid = (int)blockIdx.x & 15;
  const int j0  = cid << 5;
  const int b0g = grp << 2;
  const int w = tid >> 5, lane = tid & 31;

  // --- stage W rows plainly: smem row R = jj*3+g <- Whh row g*512 + j0+jj ---
  for (int idx = tid; idx < 96 * 128; idx += NT) {
    int R = idx >> 7, c4 = idx & 127;
    int jj = R / 3, g = R - jj * 3;
    *(float4*)(WS + R * 2048 + c4 * 16) =
        *(const float4*)(Whh + (size_t)(g * HID + j0 + jj) * HID + (c4 << 2));
  }
  if (tid < 96) {
    int jj = tid / 3, g = tid - jj * 3;
    bh[tid] = bhh[g * HID + j0 + jj];
  }
  if (tid == 0) g_flags[blockIdx.x][0] = 0u;   // clear stale replay value
  init_barrier(grp);                            // one-time; counters end at 0

  const int b_o = tid >> 5, jj_o = tid & 31;

  for (int t = 0; t < SEQT; t++) {
    const float* hsrc = (t == 0) ? h0 : &g_h[t & 1][0];
    float* hn = &g_h[(t + 1) & 1][0];

    // xg prefetch (independent of flags)
    float xr = 0.f, xz = 0.f, xn = 0.f;
    if (tid < 128) {
      const float* xgp = g_xg + ((size_t)t * BATCH + (b0g + b_o)) * G3 + j0 + jj_o;
      xr = __ldcg(xgp); xz = __ldcg(xgp + HID); xn = __ldcg(xgp + 2 * HID);
    }

    // wait for all group producers of h_t (skip at t=0: h0 is an input)
    if (t > 0) {
      if (tid < 16) {
        const unsigned* fp = &g_flags[grp * 16 + tid][0];
        unsigned v;
        do {
          asm volatile("ld.acquire.gpu.global.u32 %0,[%1];" : "=r"(v) : "l"(fp) : "memory");
        } while (v < (unsigned)t);
      }
      __syncthreads();
    }

    // --- stage group h (8KB, read once from L2) into plain [b][512] smem ---
#pragma unroll
    for (int i = 0; i < 2; i++) {
      int idx = i * NT + tid;                 // 0..511 float4s
      int b_r = idx >> 7, c4 = idx & 127;
      const float* src = hsrc + (size_t)(b0g + b_r) * HID + (c4 << 2);
      float4 v;
      asm volatile("ld.global.cg.v4.f32 {%0,%1,%2,%3},[%4];"
                   : "=f"(v.x), "=f"(v.y), "=f"(v.z), "=f"(v.w) : "l"(src));
      *(float4*)(HS + idx * 16) = v;
    }
    __syncthreads();

    // --- lane's h: k = {4*lane + 128*i}; 16 fully-unique LDS.128 ---
    ull hreg[4][8];
#pragma unroll
    for (int b = 0; b < 4; b++) {
      const char* hb = HS + b * 2048 + lane * 16;
#pragma unroll
      for (int i = 0; i < 4; i++) {
        ulonglong2 u = *(const ulonglong2*)(hb + i * 512);
        hreg[b][i * 2] = u.x; hreg[b][i * 2 + 1] = u.y;
      }
    }
    float hprev = 0.f;
    if (tid < 128) hprev = *(const float*)(HS + b_o * 2048 + (j0 + jj_o) * 4);

    // --- 12 rows x 4 batches x 16 k per lane; W LDS fully unique ---
    ull acc[48];
#pragma unroll
    for (int c = 0; c < 48; c++) acc[c] = 0ull;
#pragma unroll
    for (int rl = 0; rl < 12; rl++) {
      const char* wrow = WS + (w * 12 + rl) * 2048 + lane * 16;
      ull wu[8];
#pragma unroll
      for (int i = 0; i < 4; i++) {
        ulonglong2 u = *(const ulonglong2*)(wrow + i * 512);
        wu[i * 2] = u.x; wu[i * 2 + 1] = u.y;
      }
#pragma unroll
      for (int b = 0; b < 4; b++) {
        ull s = acc[rl * 4 + b];
#pragma unroll
        for (int u = 0; u < 8; u++) s = ffma2(wu[u], hreg[b][u], s);
        acc[rl * 4 + b] = s;
      }
    }

    // --- reduce: x+y, xor16, xor8 -> 8 partials -> smem ---
#pragma unroll
    for (int c = 0; c < 48; c++) {
      float2 p = upk2(acc[c]);
      float v = p.x + p.y;
      v += __shfl_xor_sync(0xffffffffu, v, 16);
      v += __shfl_xor_sync(0xffffffffu, v, 8);
      if (lane < 8) red[w * 384 + c * 8 + lane] = v;
    }
    __syncthreads();

    // --- gate math (threads 0..127) ---
    if (tid < 128) {
      int wj = jj_o >> 2, jl = jj_o & 3;
      const float* rp = red + wj * 384 + b_o * 8;
      float sr = 0.f, sz = 0.f, sn = 0.f;
#pragma unroll
      for (int p = 0; p < 8; p++) {
        sr += rp[(jl * 3 + 0) * 32 + p];
        sz += rp[(jl * 3 + 1) * 32 + p];
        sn += rp[(jl * 3 + 2) * 32 + p];
      }
      float rg = sigmoid_f(xr + sr + bh[jj_o * 3 + 0]);
      float zg = sigmoid_f(xz + sz + bh[jj_o * 3 + 1]);
      float ng = tanh_f(xn + rg * (sn + bh[jj_o * 3 + 2]));
      float hnew = ng + zg * (hprev - ng);
      hn[(b0g + b_o) * HID + j0 + jj_o] = hnew;
      out[((size_t)(b0g + b_o) * SEQT + t) * HID + j0 + jj_o] = hnew;
    }
    __syncthreads();   // all h stores done
    if (tid == 0) {
      unsigned* fp = &g_flags[blockIdx.x][0];
      asm volatile("st.release.gpu.global.u32 [%0],%1;" :: "l"(fp), "r"((unsigned)(t + 1)) : "memory");
    }
  }
}

extern "C" void kernel_launch(void* const* d_in, const int* in_sizes, int n_in,
                              void* d_out, int out_size) {
  (void)in_sizes; (void)n_in; (void)out_size;
  const float* input = (const float*)d_in[0];
  const float* h0    = (const float*)d_in[1];
  const float* wih   = (const float*)d_in[2];
  const float* whh   = (const float*)d_in[3];
  const float* bih   = (const float*)d_in[4];
  const float* bhh   = (const float*)d_in[5];
  float* out = (float*)d_out;

  cudaFuncSetAttribute(gru_scan, cudaFuncAttributeMaxDynamicSharedMemorySize, SCAN_SMEM);

  dim3 gA(G3 / 128, (BATCH * SEQT) / 128);
  gemm_xgates<<<gA, 256>>>(input, wih, bih);
  gru_scan<<<NGRP * GSZ2, NT, SCAN_SMEM>>>(whh, bhh, h0, out);
}

// round 14
// speedup vs baseline: 3.3087x; 1.0612x over previous
#include <cuda_runtime.h>
#include <cstdint>
#include <cstddef>

#define BATCH 32
#define SEQT  2048
#define INSZ  512
#define HID   512
#define G3    1536
#define NT    256
#define NGRP  8
#define GSZ2  16
typedef unsigned long long ull;

__device__ float g_xg[(size_t)SEQT * BATCH * G3];   // [t][b][3H]
__device__ float g_h[2][BATCH * HID];
__device__ unsigned g_flags[128][32];               // per-CTA step flag, 128B stride
__device__ unsigned g_bcount[NGRP][32];             // one-time init barrier (ends at 0)
__device__ unsigned g_bgen[NGRP][32];

// ---- packed f32x2 helpers ----
__device__ __forceinline__ ull pk2(float x, float y) {
  ull r; asm("mov.b64 %0, {%1,%2};" : "=l"(r) : "f"(x), "f"(y)); return r;
}
__device__ __forceinline__ ull ffma2(ull a, ull b, ull c) {
  ull d; asm("fma.rn.f32x2 %0, %1, %2, %3;" : "=l"(d) : "l"(a), "l"(b), "l"(c)); return d;
}
__device__ __forceinline__ float2 upk2(ull v) {
  float x, y; asm("mov.b64 {%0,%1}, %2;" : "=f"(x), "=f"(y) : "l"(v));
  return make_float2(x, y);
}
__device__ __forceinline__ float sigmoid_f(float x) { return 1.f / (1.f + __expf(-x)); }
__device__ __forceinline__ float tanh_f(float x) {
  float e = __expf(-2.f * x); return (1.f - e) / (1.f + e);
}

// =============================================================
// Kernel A: x_gates GEMM (measured 2.7 ms — unchanged)
// =============================================================
__global__ __launch_bounds__(256, 1) void gemm_xgates(
    const float* __restrict__ A, const float* __restrict__ Wih,
    const float* __restrict__ bih) {
  __shared__ ull As2[2][8][128];
  __shared__ ull Bs2[2][8][128];

  const int tid = threadIdx.x;
  const int m0 = blockIdx.y << 7, n0 = blockIdx.x << 7;
  const int tx = tid & 15, ty = tid >> 4;
  const int lrow = tid & 127, lk4 = (tid >> 7) << 3;
  const int ty4 = ty * 4;

  const float* Ap = A + (size_t)(m0 + lrow) * INSZ + lk4;
  const float* Bp = Wih + (size_t)(n0 + lrow) * INSZ + lk4;

  ull acc[64];
#pragma unroll
  for (int i = 0; i < 64; i++) acc[i] = 0ull;

  float4 la0 = *(const float4*)(Ap), la1 = *(const float4*)(Ap + 4);
  float4 lb0 = *(const float4*)(Bp), lb1 = *(const float4*)(Bp + 4);
  {
    int kk = lk4 >> 1;
    As2[0][kk + 0][lrow] = pk2(la0.x, la0.y);
    As2[0][kk + 1][lrow] = pk2(la0.z, la0.w);
    As2[0][kk + 2][lrow] = pk2(la1.x, la1.y);
    As2[0][kk + 3][lrow] = pk2(la1.z, la1.w);
    Bs2[0][kk + 0][lrow] = pk2(lb0.x, lb0.y);
    Bs2[0][kk + 1][lrow] = pk2(lb0.z, lb0.w);
    Bs2[0][kk + 2][lrow] = pk2(lb1.x, lb1.y);
    Bs2[0][kk + 3][lrow] = pk2(lb1.z, lb1.w);
  }
  __syncthreads();

  for (int kt = 0; kt < 32; kt++) {
    const int cur = kt & 1, nxt = cur ^ 1;
    if (kt < 31) {
      Ap += 16; Bp += 16;
      la0 = *(const float4*)(Ap); la1 = *(const float4*)(Ap + 4);
      lb0 = *(const float4*)(Bp); lb1 = *(const float4*)(Bp + 4);
    }
#pragma unroll
    for (int kk = 0; kk < 8; kk++) {
      ulonglong2 aa0 = *(const ulonglong2*)&As2[cur][kk][ty4];
      ulonglong2 aa1 = *(const ulonglong2*)&As2[cur][kk][ty4 + 2];
      ulonglong2 aa2 = *(const ulonglong2*)&As2[cur][kk][64 + ty4];
      ulonglong2 aa3 = *(const ulonglong2*)&As2[cur][kk][64 + ty4 + 2];
      ulonglong2 bb0 = *(const ulonglong2*)&Bs2[cur][kk][tx * 4];
      ulonglong2 bb1 = *(const ulonglong2*)&Bs2[cur][kk][tx * 4 + 2];
      ulonglong2 bb2 = *(const ulonglong2*)&Bs2[cur][kk][64 + tx * 4];
      ulonglong2 bb3 = *(const ulonglong2*)&Bs2[cur][kk][64 + tx * 4 + 2];
      ull a2[8] = {aa0.x, aa0.y, aa1.x, aa1.y, aa2.x, aa2.y, aa3.x, aa3.y};
      ull b2[8] = {bb0.x, bb0.y, bb1.x, bb1.y, bb2.x, bb2.y, bb3.x, bb3.y};
#pragma unroll
      for (int i = 0; i < 8; i++)
#pragma unroll
        for (int j = 0; j < 8; j++)
          acc[i * 8 + j] = ffma2(a2[i], b2[j], acc[i * 8 + j]);
    }
    if (kt < 31) {
      int kk = lk4 >> 1;
      As2[nxt][kk + 0][lrow] = pk2(la0.x, la0.y);
      As2[nxt][kk + 1][lrow] = pk2(la0.z, la0.w);
      As2[nxt][kk + 2][lrow] = pk2(la1.x, la1.y);
      As2[nxt][kk + 3][lrow] = pk2(la1.z, la1.w);
      Bs2[nxt][kk + 0][lrow] = pk2(lb0.x, lb0.y);
      Bs2[nxt][kk + 1][lrow] = pk2(lb0.z, lb0.w);
      Bs2[nxt][kk + 2][lrow] = pk2(lb1.x, lb1.y);
      Bs2[nxt][kk + 3][lrow] = pk2(lb1.z, lb1.w);
    }
    __syncthreads();
  }

  float4 bia0 = *(const float4*)(bih + n0 + tx * 4);
  float4 bia1 = *(const float4*)(bih + n0 + 64 + tx * 4);
#pragma unroll
  for (int i = 0; i < 8; i++) {
    int m = m0 + ((i < 4) ? (ty4 + i) : (64 + ty4 + i - 4));
    int b = m >> 11, t = m & 2047;
    float* orow = g_xg + ((size_t)t * BATCH + b) * G3 + n0;
    float2 p; float4 o0, o1;
    p = upk2(acc[i * 8 + 0]); o0.x = p.x + p.y + bia0.x;
    p = upk2(acc[i * 8 + 1]); o0.y = p.x + p.y + bia0.y;
    p = upk2(acc[i * 8 + 2]); o0.z = p.x + p.y + bia0.z;
    p = upk2(acc[i * 8 + 3]); o0.w = p.x + p.y + bia0.w;
    p = upk2(acc[i * 8 + 4]); o1.x = p.x + p.y + bia1.x;
    p = upk2(acc[i * 8 + 5]); o1.y = p.x + p.y + bia1.y;
    p = upk2(acc[i * 8 + 6]); o1.z = p.x + p.y + bia1.z;
    p = upk2(acc[i * 8 + 7]); o1.w = p.x + p.y + bia1.w;
    *(float4*)(orow + tx * 4) = o0;
    *(float4*)(orow + 64 + tx * 4) = o1;
  }
}

// =============================================================
// Kernel B: persistent GRU scan — conflict-free reduction layout
// 8 groups x 16 CTAs; group = 4 batches; CTA = 32 cols; warp = 12 rows
// Lane owns k in {4*lane + 128*i, i=0..3}
// red layout: OFF(b,w,rl,p) = b*800 + w*100 + rl*8 + p   (padded stride)
// smem: WS 192KB @0 | HS 8KB @196608 | red 12.8KB @204800 | bh @217600
// =============================================================
__device__ __forceinline__ void init_barrier(int grp) {
  __syncthreads();
  if (threadIdx.x == 0) {
    unsigned* cnt = &g_bcount[grp][0];
    unsigned* gen = &g_bgen[grp][0];
    unsigned g0;
    asm volatile("ld.acquire.gpu.global.u32 %0,[%1];" : "=r"(g0) : "l"(gen) : "memory");
    unsigned a;
    asm volatile("atom.add.acq_rel.gpu.global.u32 %0,[%1],1;" : "=r"(a) : "l"(cnt) : "memory");
    if (a == GSZ2 - 1) {
      asm volatile("st.relaxed.gpu.global.u32 [%0],0;" :: "l"(cnt) : "memory");
      unsigned tmp;
      asm volatile("atom.add.release.gpu.global.u32 %0,[%1],1;" : "=r"(tmp) : "l"(gen) : "memory");
    } else {
      unsigned cur;
      do {
        asm volatile("ld.acquire.gpu.global.u32 %0,[%1];" : "=r"(cur) : "l"(gen) : "memory");
      } while (cur == g0);
    }
  }
  __syncthreads();
}

#define SCAN_SMEM 217984

__global__ __launch_bounds__(NT, 1)
void gru_scan(const float* __restrict__ Whh, const float* __restrict__ bhh,
              const float* __restrict__ h0, float* __restrict__ out) {
  extern __shared__ char smem[];
  char* WS = smem;                      // 96 rows x 2048B, plain row-major
  char* HS = smem + 196608;             // [b][512 cols], plain row-major, 8KB
  float* red = (float*)(smem + 204800); // [b][w][rl][8], w-stride 100 floats
  float* bh  = (float*)(smem + 217600); // [96] = [jj*3+g]

  const int tid = threadIdx.x;
  const int grp = (int)blockIdx.x >> 4;
  const int cid = (int)blockIdx.x & 15;
  const int j0  = cid << 5;
  const int b0g = grp << 2;
  const int w = tid >> 5, lane = tid & 31;

  // --- stage W rows plainly: smem row R = jj*3+g <- Whh row g*512 + j0+jj ---
  for (int idx = tid; idx < 96 * 128; idx += NT) {
    int R = idx >> 7, c4 = idx & 127;
    int jj = R / 3, g = R - jj * 3;
    *(float4*)(WS + R * 2048 + c4 * 16) =
        *(const float4*)(Whh + (size_t)(g * HID + j0 + jj) * HID + (c4 << 2));
  }
  if (tid < 96) {
    int jj = tid / 3, g = tid - jj * 3;
    bh[tid] = bhh[g * HID + j0 + jj];
  }
  if (tid == 0) g_flags[blockIdx.x][0] = 0u;   // clear stale replay value
  init_barrier(grp);                            // one-time; counters end at 0

  const int b_o = tid >> 5, jj_o = tid & 31;

  for (int t = 0; t < SEQT; t++) {
    const float* hsrc = (t == 0) ? h0 : &g_h[t & 1][0];
    float* hn = &g_h[(t + 1) & 1][0];

    // xg prefetch (independent of flags)
    float xr = 0.f, xz = 0.f, xn = 0.f;
    if (tid < 128) {
      const float* xgp = g_xg + ((size_t)t * BATCH + (b0g + b_o)) * G3 + j0 + jj_o;
      xr = __ldcg(xgp); xz = __ldcg(xgp + HID); xn = __ldcg(xgp + 2 * HID);
    }

    // wait for all group producers of h_t (skip at t=0: h0 is an input)
    if (t > 0) {
      if (tid < 16) {
        const unsigned* fp = &g_flags[grp * 16 + tid][0];
        unsigned v;
        do {
          asm volatile("ld.acquire.gpu.global.u32 %0,[%1];" : "=r"(v) : "l"(fp) : "memory");
        } while (v < (unsigned)t);
      }
      __syncthreads();
    }

    // --- stage group h (8KB, read once from L2) into plain [b][512] smem ---
#pragma unroll
    for (int i = 0; i < 2; i++) {
      int idx = i * NT + tid;                 // 0..511 float4s
      const float* src = hsrc + (size_t)b0g * HID + ((size_t)idx << 2);
      float4 v;
      asm volatile("ld.global.cg.v4.f32 {%0,%1,%2,%3},[%4];"
                   : "=f"(v.x), "=f"(v.y), "=f"(v.z), "=f"(v.w) : "l"(src));
      *(float4*)(HS + idx * 16) = v;
    }
    __syncthreads();

    // --- lane's h: k = {4*lane + 128*i}; 16 fully-unique LDS.128 ---
    ull hreg[4][8];
#pragma unroll
    for (int b = 0; b < 4; b++) {
      const char* hb = HS + b * 2048 + lane * 16;
#pragma unroll
      for (int i = 0; i < 4; i++) {
        ulonglong2 u = *(const ulonglong2*)(hb + i * 512);
        hreg[b][i * 2] = u.x; hreg[b][i * 2 + 1] = u.y;
      }
    }
    float hprev = 0.f;
    if (tid < 128) hprev = *(const float*)(HS + b_o * 2048 + (j0 + jj_o) * 4);

    // --- 12 rows x 4 batches x 16 k per lane; W LDS fully unique ---
    ull acc[48];
#pragma unroll
    for (int c = 0; c < 48; c++) acc[c] = 0ull;
#pragma unroll
    for (int rl = 0; rl < 12; rl++) {
      const char* wrow = WS + (w * 12 + rl) * 2048 + lane * 16;
      ull wu[8];
#pragma unroll
      for (int i = 0; i < 4; i++) {
        ulonglong2 u = *(const ulonglong2*)(wrow + i * 512);
        wu[i * 2] = u.x; wu[i * 2 + 1] = u.y;
      }
#pragma unroll
      for (int b = 0; b < 4; b++) {
        ull s = acc[rl * 4 + b];
#pragma unroll
        for (int u = 0; u < 8; u++) s = ffma2(wu[u], hreg[b][u], s);
        acc[rl * 4 + b] = s;
      }
    }

    // --- reduce: x+y, xor16, xor8 -> 8 partials -> padded smem layout ---
#pragma unroll
    for (int c = 0; c < 48; c++) {
      float2 p = upk2(acc[c]);
      float v = p.x + p.y;
      v += __shfl_xor_sync(0xffffffffu, v, 16);
      v += __shfl_xor_sync(0xffffffffu, v, 8);
      if (lane < 8) {
        int rl = c >> 2, b = c & 3;
        red[b * 800 + w * 100 + rl * 8 + lane] = v;
      }
    }
    __syncthreads();

    // --- gate math (threads 0..127): 24 contiguous floats, 6x LDS.128 ---
    if (tid < 128) {
      int wj = jj_o >> 2, jl = jj_o & 3;
      const float4* rp = (const float4*)(red + b_o * 800 + wj * 100 + jl * 24);
      float4 q0 = rp[0], q1 = rp[1];   // g=0 partials
      float4 q2 = rp[2], q3 = rp[3];   // g=1
      float4 q4 = rp[4], q5 = rp[5];   // g=2
      float sr = (q0.x + q0.y) + (q0.z + q0.w) + (q1.x + q1.y) + (q1.z + q1.w);
      float sz = (q2.x + q2.y) + (q2.z + q2.w) + (q3.x + q3.y) + (q3.z + q3.w);
      float sn = (q4.x + q4.y) + (q4.z + q4.w) + (q5.x + q5.y) + (q5.z + q5.w);
      float rg = sigmoid_f(xr + sr + bh[jj_o * 3 + 0]);
      float zg = sigmoid_f(xz + sz + bh[jj_o * 3 + 1]);
      float ng = tanh_f(xn + rg * (sn + bh[jj_o * 3 + 2]));
      float hnew = ng + zg * (hprev - ng);
      hn[(b0g + b_o) * HID + j0 + jj_o] = hnew;
      out[((size_t)(b0g + b_o) * SEQT + t) * HID + j0 + jj_o] = hnew;
    }
    __syncthreads();   // all h stores done
    if (tid == 0) {
      unsigned* fp = &g_flags[blockIdx.x][0];
      asm volatile("st.release.gpu.global.u32 [%0],%1;" :: "l"(fp), "r"((unsigned)(t + 1)) : "memory");
    }
  }
}

extern "C" void kernel_launch(void* const* d_in, const int* in_sizes, int n_in,
                              void* d_out, int out_size) {
  (void)in_sizes; (void)n_in; (void)out_size;
  const float* input = (const float*)d_in[0];
  const float* h0    = (const float*)d_in[1];
  const float* wih   = (const float*)d_in[2];
  const float* whh   = (const float*)d_in[3];
  const float* bih   = (const float*)d_in[4];
  const float* bhh   = (const float*)d_in[5];
  float* out = (float*)d_out;

  cudaFuncSetAttribute(gru_scan, cudaFuncAttributeMaxDynamicSharedMemorySize, SCAN_SMEM);

  dim3 gA(G3 / 128, (BATCH * SEQT) / 128);
  gemm_xgates<<<gA, 256>>>(input, wih, bih);
  gru_scan<<<NGRP * GSZ2, NT, SCAN_SMEM>>>(whh, bhh, h0, out);
}